// round 1
// baseline (speedup 1.0000x reference)
#include <cuda_runtime.h>

#define Bsz 256
#define Tn  6000
#define Ln  2000
#define DM  64
#define DI  128
#define NSt 8
#define DCk 4
#define NBk 2
#define TL  50   // rows per tile in k2 (2000 % 50 == 0)

// ---------------- scratch (static device allocations) ----------------
__device__ __align__(16) float g_z[2][(size_t)Bsz * Ln * DM];      // residual stream f/b
__device__ __align__(16) float g_xiraw[2][(size_t)Bsz * Ln * DI];  // pre-conv xi; reused as y after k2
__device__ __align__(16) float g_szg[2][(size_t)Bsz * Ln * DI];    // silu(zg)
__device__ __align__(16) float g_xi[2][(size_t)Bsz * Ln * DI];     // post conv+silu
__device__ __align__(16) float g_dt[2][(size_t)Bsz * Ln * DI];     // softplus dt
__device__ __align__(16) float g_bc[2][(size_t)Bsz * Ln * 16];     // [B(8) | C(8)] per (b,l)

__device__ __forceinline__ float silu_f(float v) {
    return __fdividef(v, 1.0f + __expf(-v));
}

// ---------------- k0: front conv (stride 3, VALID) -> zf, zb(reversed) ----
__global__ void k_conv(const float* __restrict__ x, const float* __restrict__ w,
                       const float* __restrict__ cb) {
    size_t idx = (size_t)blockIdx.x * blockDim.x + threadIdx.x;
    if (idx >= (size_t)Bsz * Ln * DM) return;
    int d = (int)(idx & (DM - 1));
    size_t bl = idx >> 6;
    int l = (int)(bl % Ln);
    int b = (int)(bl / Ln);
    const float* xp = x + (size_t)b * Tn + 3 * (size_t)l;
    float v = cb[d] + xp[0] * w[d * 3 + 0] + xp[1] * w[d * 3 + 1] + xp[2] * w[d * 3 + 2];
    g_z[0][bl * DM + d] = v;
    g_z[1][((size_t)b * Ln + (Ln - 1 - l)) * DM + d] = v;
}

// ---------------- k1: LN + in_proj (64->256) + split + silu(zg) ----------
// block: 256 thr = 8 warps, each warp does 4 rows. grid: (B*L/32, 2 chains)
__global__ void k1_ln_inproj(int p,
                             const float* __restrict__ f_lnw, const float* __restrict__ f_lnb,
                             const float* __restrict__ f_inw,
                             const float* __restrict__ b_lnw, const float* __restrict__ b_lnb,
                             const float* __restrict__ b_inw) {
    extern __shared__ float sm1[];
    float* Ws = sm1;            // [256][65] padded: Ws[e*65+d]
    float* us = sm1 + 256 * 65; // [32 rows][64]
    int c = blockIdx.y;
    const float* lnw = (c ? b_lnw : f_lnw) + p * DM;
    const float* lnb = (c ? b_lnb : f_lnb) + p * DM;
    const float* inw = (c ? b_inw : f_inw) + (size_t)p * 256 * DM;

    for (int s = threadIdx.x; s < 256 * DM; s += blockDim.x) {
        int e = s >> 6, d = s & 63;
        Ws[e * 65 + d] = inw[s];
    }
    __syncthreads();

    int warp = threadIdx.x >> 5, lane = threadIdx.x & 31;
    size_t row0 = (size_t)blockIdx.x * 32 + warp * 4;
    const float* zb = g_z[c];
    float lw0 = lnw[lane], lw1 = lnw[lane + 32];
    float lb0 = lnb[lane], lb1 = lnb[lane + 32];
    float* up = us + warp * 4 * 64;

#pragma unroll
    for (int r = 0; r < 4; r++) {
        size_t row = row0 + r;
        float v0 = zb[row * DM + lane], v1 = zb[row * DM + lane + 32];
        float s = v0 + v1, ss = v0 * v0 + v1 * v1;
#pragma unroll
        for (int o = 16; o; o >>= 1) {
            s  += __shfl_xor_sync(0xffffffffu, s, o);
            ss += __shfl_xor_sync(0xffffffffu, ss, o);
        }
        float mean = s * (1.0f / 64.0f);
        float var  = ss * (1.0f / 64.0f) - mean * mean;
        float rstd = rsqrtf(var + 1e-5f);
        up[r * 64 + lane]      = (v0 - mean) * rstd * lw0 + lb0;
        up[r * 64 + lane + 32] = (v1 - mean) * rstd * lw1 + lb1;
    }
    __syncwarp();

    float acc[8][4];
#pragma unroll
    for (int j = 0; j < 8; j++)
#pragma unroll
        for (int r = 0; r < 4; r++) acc[j][r] = 0.0f;

#pragma unroll 4
    for (int d = 0; d < 64; d++) {
        float u0 = up[d], u1 = up[64 + d], u2 = up[128 + d], u3 = up[192 + d];
#pragma unroll
        for (int j = 0; j < 8; j++) {
            float w = Ws[(j * 32 + lane) * 65 + d];
            acc[j][0] = fmaf(w, u0, acc[j][0]);
            acc[j][1] = fmaf(w, u1, acc[j][1]);
            acc[j][2] = fmaf(w, u2, acc[j][2]);
            acc[j][3] = fmaf(w, u3, acc[j][3]);
        }
    }

    float* xiraw = g_xiraw[c];
    float* szg = g_szg[c];
#pragma unroll
    for (int j = 0; j < 4; j++) {
        int e = j * 32 + lane;
#pragma unroll
        for (int r = 0; r < 4; r++) xiraw[(row0 + r) * DI + e] = acc[j][r];
    }
#pragma unroll
    for (int j = 4; j < 8; j++) {
        int e = (j - 4) * 32 + lane;
#pragma unroll
        for (int r = 0; r < 4; r++) szg[(row0 + r) * DI + e] = silu_f(acc[j][r]);
    }
}

// ---------------- k2: depthwise causal conv(4)+silu, xp proj(->20), dt ----
// block: 256 thr handles (b, 50-row tile). grid: (B*40, 2)
__global__ void k2_conv_xp_dt(int p,
                              const float* __restrict__ f_cvw, const float* __restrict__ f_cvb,
                              const float* __restrict__ f_xpw, const float* __restrict__ f_dtw,
                              const float* __restrict__ f_dtb,
                              const float* __restrict__ b_cvw, const float* __restrict__ b_cvb,
                              const float* __restrict__ b_xpw, const float* __restrict__ b_dtw,
                              const float* __restrict__ b_dtb) {
    extern __shared__ float sm2[];
    float* raw = sm2;                    // (TL+3)*128
    float* xis = raw + (TL + 3) * DI;    // TL*128
    float* bcr = xis + TL * DI;          // TL*20
    float* xw  = bcr + TL * 20;          // [128][20] transposed
    float* dtw = xw + DI * 20;           // 128*4
    float* cvw = dtw + DI * 4;           // 128*4
    float* cvb = cvw + DI * 4;           // 128
    float* dtb = cvb + DI;               // 128

    int c = blockIdx.y;
    const float* cvwg = (c ? b_cvw : f_cvw) + (size_t)p * DI * DCk;
    const float* cvbg = (c ? b_cvb : f_cvb) + p * DI;
    const float* xpwg = (c ? b_xpw : f_xpw) + (size_t)p * 20 * DI;
    const float* dtwg = (c ? b_dtw : f_dtw) + (size_t)p * DI * 4;
    const float* dtbg = (c ? b_dtb : f_dtb) + p * DI;

    for (int s = threadIdx.x; s < 20 * DI; s += blockDim.x) {
        int e = s >> 7, d = s & 127;
        xw[d * 20 + e] = xpwg[s];
    }
    for (int s = threadIdx.x; s < DI * 4; s += blockDim.x) { dtw[s] = dtwg[s]; cvw[s] = cvwg[s]; }
    for (int s = threadIdx.x; s < DI; s += blockDim.x) { cvb[s] = cvbg[s]; dtb[s] = dtbg[s]; }

    int chunk = blockIdx.x % (Ln / TL);
    int b = blockIdx.x / (Ln / TL);
    int l0 = chunk * TL;
    const float* xiraw = g_xiraw[c] + (size_t)b * Ln * DI;

    for (int s = threadIdx.x; s < (TL + 3) * DI; s += blockDim.x) {
        int r = s >> 7, d = s & 127;
        int l = l0 - 3 + r;
        raw[s] = (l >= 0) ? xiraw[(size_t)l * DI + d] : 0.0f;
    }
    __syncthreads();

    float* xig = g_xi[c] + (size_t)b * Ln * DI;
    for (int s = threadIdx.x; s < TL * DI; s += blockDim.x) {
        int r = s >> 7, d = s & 127;
        float a = cvb[d];
#pragma unroll
        for (int j = 0; j < 4; j++) a = fmaf(raw[(r + j) * DI + d], cvw[d * 4 + j], a);
        a = silu_f(a);
        xis[s] = a;
        xig[(size_t)(l0 + r) * DI + d] = a;
    }
    __syncthreads();

    int warp = threadIdx.x >> 5, lane = threadIdx.x & 31;
    float* bcg = g_bc[c] + (size_t)b * Ln * 16;
    for (int r = warp; r < TL; r += 8) {
        if (lane < 20) {
            float a = 0.0f;
            const float* xr = xis + r * DI;
#pragma unroll 8
            for (int d = 0; d < DI; d++) a = fmaf(xr[d], xw[d * 20 + lane], a);
            bcr[r * 20 + lane] = a;
            if (lane >= 4) bcg[(size_t)(l0 + r) * 16 + (lane - 4)] = a;
        }
    }
    __syncthreads();

    float* dtg = g_dt[c] + (size_t)b * Ln * DI;
    for (int s = threadIdx.x; s < TL * DI; s += blockDim.x) {
        int r = s >> 7, d = s & 127;
        const float* q = bcr + r * 20;
        float v = dtb[d];
#pragma unroll
        for (int j = 0; j < 4; j++) v = fmaf(q[j], dtw[d * 4 + j], v);
        // softplus = max(v,0) + log1p(exp(-|v|))
        v = fmaxf(v, 0.0f) + log1pf(__expf(-fabsf(v)));
        dtg[(size_t)(l0 + r) * DI + d] = v;
    }
}

// ---------------- k3: selective scan, fused * silu(zg). y -> g_xiraw ------
// block: 128 thr (one per d) handles one (b, chain). grid: (B, 2)
__global__ void k3_scan(int p,
                        const float* __restrict__ f_alog, const float* __restrict__ f_Dp,
                        const float* __restrict__ b_alog, const float* __restrict__ b_Dp) {
    int c = blockIdx.y;
    int b = blockIdx.x;
    int d = threadIdx.x;
    const float* alog = (c ? b_alog : f_alog) + ((size_t)p * DI + d) * NSt;
    float Dv = ((c ? b_Dp : f_Dp) + p * DI)[d];

    float A[NSt];
    bool fast = true;
#pragma unroll
    for (int n = 0; n < NSt; n++) {
        A[n] = -__expf(alog[n]);
        float tgt = (float)(n + 1);
        if (fabsf(A[n] + tgt) > 1e-5f * tgt) fast = false;
    }
    float h[NSt];
#pragma unroll
    for (int n = 0; n < NSt; n++) h[n] = 0.0f;

    const float* dtp = g_dt[c] + (size_t)b * Ln * DI + d;
    const float* xip = g_xi[c] + (size_t)b * Ln * DI + d;
    const float* sgp = g_szg[c] + (size_t)b * Ln * DI + d;
    float* yp = g_xiraw[c] + (size_t)b * Ln * DI + d;
    const float4* bcp = (const float4*)(g_bc[c] + (size_t)b * Ln * 16);

    if (fast) {
#pragma unroll 2
        for (int l = 0; l < Ln; l++) {
            float dtv = dtp[(size_t)l * DI];
            float xv  = xip[(size_t)l * DI];
            float sg  = sgp[(size_t)l * DI];
            float4 q0 = bcp[l * 4 + 0], q1 = bcp[l * 4 + 1];
            float4 q2 = bcp[l * 4 + 2], q3 = bcp[l * 4 + 3];
            float Bv[8] = {q0.x, q0.y, q0.z, q0.w, q1.x, q1.y, q1.z, q1.w};
            float Cv[8] = {q2.x, q2.y, q2.z, q2.w, q3.x, q3.y, q3.z, q3.w};
            float dx = dtv * xv;
            float y = xv * Dv;
            float w = __expf(-dtv);  // A[n] == -(n+1): exp(dt*A[n]) = w^(n+1)
            float e = w;
#pragma unroll
            for (int n = 0; n < NSt; n++) {
                h[n] = fmaf(h[n], e, dx * Bv[n]);
                y = fmaf(h[n], Cv[n], y);
                e *= w;
            }
            yp[(size_t)l * DI] = y * sg;
        }
    } else {
        for (int l = 0; l < Ln; l++) {
            float dtv = dtp[(size_t)l * DI];
            float xv  = xip[(size_t)l * DI];
            float sg  = sgp[(size_t)l * DI];
            float4 q0 = bcp[l * 4 + 0], q1 = bcp[l * 4 + 1];
            float4 q2 = bcp[l * 4 + 2], q3 = bcp[l * 4 + 3];
            float Bv[8] = {q0.x, q0.y, q0.z, q0.w, q1.x, q1.y, q1.z, q1.w};
            float Cv[8] = {q2.x, q2.y, q2.z, q2.w, q3.x, q3.y, q3.z, q3.w};
            float dx = dtv * xv;
            float y = xv * Dv;
#pragma unroll
            for (int n = 0; n < NSt; n++) {
                float e = __expf(dtv * A[n]);
                h[n] = fmaf(h[n], e, dx * Bv[n]);
                y = fmaf(h[n], Cv[n], y);
            }
            yp[(size_t)l * DI] = y * sg;
        }
    }
}

// ---------------- k4: out proj (128->64) + residual into z ---------------
__global__ void k4_outproj(int p, const float* __restrict__ f_ow, const float* __restrict__ b_ow) {
    extern __shared__ float sm4[];
    float* ws = sm4;              // [128][65]: ws[d*65+m]
    float* us = sm4 + DI * 65;    // [32 rows][128]
    int c = blockIdx.y;
    const float* ow = (c ? b_ow : f_ow) + (size_t)p * DM * DI;

    for (int s = threadIdx.x; s < DM * DI; s += blockDim.x) {
        int m = s >> 7, d = s & 127;
        ws[d * 65 + m] = ow[s];
    }
    __syncthreads();

    int warp = threadIdx.x >> 5, lane = threadIdx.x & 31;
    size_t row0 = (size_t)blockIdx.x * 32 + warp * 4;
    const float* yb = g_xiraw[c];
    float* zb = g_z[c];
    float* up = us + warp * 4 * DI;
    for (int s = lane; s < 4 * DI; s += 32) {
        int r = s >> 7, d = s & 127;
        up[s] = yb[(row0 + r) * DI + d];
    }
    __syncwarp();

    float acc[2][4];
#pragma unroll
    for (int j = 0; j < 2; j++)
#pragma unroll
        for (int r = 0; r < 4; r++) acc[j][r] = zb[(row0 + r) * DM + j * 32 + lane];

#pragma unroll 4
    for (int d = 0; d < DI; d++) {
        float u0 = up[d], u1 = up[DI + d], u2 = up[2 * DI + d], u3 = up[3 * DI + d];
#pragma unroll
        for (int j = 0; j < 2; j++) {
            float w = ws[d * 65 + j * 32 + lane];
            acc[j][0] = fmaf(w, u0, acc[j][0]);
            acc[j][1] = fmaf(w, u1, acc[j][1]);
            acc[j][2] = fmaf(w, u2, acc[j][2]);
            acc[j][3] = fmaf(w, u3, acc[j][3]);
        }
    }
#pragma unroll
    for (int j = 0; j < 2; j++)
#pragma unroll
        for (int r = 0; r < 4; r++) zb[(row0 + r) * DM + j * 32 + lane] = acc[j][r];
}

// ---------------- k5: classifier ------------------------------------------
__global__ void k5_cls(const float* __restrict__ cw, const float* __restrict__ cb,
                       float* __restrict__ out) {
    __shared__ float hh[2 * DM];
    int b = blockIdx.x;
    int t = threadIdx.x;
    if (t < DM) hh[t] = g_z[0][((size_t)b * Ln + (Ln - 1)) * DM + t];
    else if (t < 2 * DM) hh[t] = g_z[1][((size_t)b * Ln + (Ln - 1)) * DM + (t - DM)];
    __syncthreads();
    float a = cb[t];
    const float* wr = cw + (size_t)t * 2 * DM;
#pragma unroll 8
    for (int j = 0; j < 2 * DM; j++) a = fmaf(hh[j], wr[j], a);
    out[(size_t)b * 256 + t] = a;
}

// ---------------- launch ---------------------------------------------------
extern "C" void kernel_launch(void* const* d_in, const int* in_sizes, int n_in,
                              void* d_out, int out_size) {
    const float* x      = (const float*)d_in[0];
    const float* conv_w = (const float*)d_in[1];
    const float* conv_b = (const float*)d_in[2];
    const float* F[11];
    const float* Bp[11];
    for (int i = 0; i < 11; i++) {
        F[i]  = (const float*)d_in[3 + i];
        Bp[i] = (const float*)d_in[14 + i];
    }
    const float* cls_w = (const float*)d_in[25];
    const float* cls_b = (const float*)d_in[26];
    float* out = (float*)d_out;

    const int smem1 = (256 * 65 + 32 * 64) * 4;
    const int smem2 = ((TL + 3) * DI + TL * DI + TL * 20 + DI * 20 + DI * 4 + DI * 4 + DI + DI) * 4;
    const int smem4 = (DI * 65 + 32 * DI) * 4;
    cudaFuncSetAttribute(k1_ln_inproj, cudaFuncAttributeMaxDynamicSharedMemorySize, smem1);
    cudaFuncSetAttribute(k2_conv_xp_dt, cudaFuncAttributeMaxDynamicSharedMemorySize, smem2);
    cudaFuncSetAttribute(k4_outproj, cudaFuncAttributeMaxDynamicSharedMemorySize, smem4);

    k_conv<<<(Bsz * Ln * DM + 255) / 256, 256>>>(x, conv_w, conv_b);

    for (int p = 0; p < NBk; p++) {
        k1_ln_inproj<<<dim3(Bsz * Ln / 32, 2), 256, smem1>>>(
            p, F[0], F[1], F[2], Bp[0], Bp[1], Bp[2]);
        k2_conv_xp_dt<<<dim3(Bsz * (Ln / TL), 2), 256, smem2>>>(
            p, F[3], F[4], F[5], F[6], F[7], Bp[3], Bp[4], Bp[5], Bp[6], Bp[7]);
        k3_scan<<<dim3(Bsz, 2), DI>>>(p, F[8], F[9], Bp[8], Bp[9]);
        k4_outproj<<<dim3(Bsz * Ln / 32, 2), 256, smem4>>>(p, F[10], Bp[10]);
    }

    k5_cls<<<Bsz, 256>>>(cls_w, cls_b, out);
}

// round 2
// speedup vs baseline: 1.0262x; 1.0262x over previous
#include <cuda_runtime.h>
#include <string.h>

typedef unsigned long long ull;

#define Bsz 256
#define Tn  6000
#define Ln  2000
#define DM  64
#define DI  128
#define NSt 8
#define NBk 2
#define TL  50    // rows per tile in k2
#define CHK 100   // scan chunk length
#define NCH 20    // chunks per sequence (CHK*NCH == Ln)

// ---------------- scratch (static device allocations) ----------------
__device__ __align__(16) float g_z[2][(size_t)Bsz * Ln * DM];      // residual stream f/b
__device__ __align__(16) float g_xiraw[2][(size_t)Bsz * Ln * DI];  // pre-conv xi; reused as y after scan
__device__ __align__(16) float g_szg[2][(size_t)Bsz * Ln * DI];    // silu(zg)
__device__ __align__(16) float g_xi[2][(size_t)Bsz * Ln * DI];     // post conv+silu
__device__ __align__(16) float g_dt[2][(size_t)Bsz * Ln * DI];     // dt; overwritten with cumsum S by k3a
__device__ __align__(16) float g_bc[2][(size_t)Bsz * Ln * 16];     // [B(8) | C(8)] per (b,l)
__device__ __align__(16) float g_hf[2][(size_t)Bsz * NCH * DI * NSt]; // chunk-final local states
__device__ __align__(16) float g_hi[2][(size_t)Bsz * NCH * DI * NSt]; // chunk-initial true states
__device__ __align__(16) float g_A[2][DI * NSt];
__device__ int g_fast[2][DI];

__device__ __forceinline__ float silu_f(float v) {
    return __fdividef(v, 1.0f + __expf(-v));
}
__device__ __forceinline__ void fma2(ull& d, ull a, ull b) {
    asm("fma.rn.f32x2 %0, %1, %2, %0;" : "+l"(d) : "l"(a), "l"(b));
}
__device__ __forceinline__ float2 up2(ull v) { float2 f; memcpy(&f, &v, 8); return f; }
__device__ __forceinline__ ull pk2(float x, float y) { float2 f = make_float2(x, y); ull v; memcpy(&v, &f, 8); return v; }

// ---------------- k0: front conv (stride 3, VALID) -> zf, zb(reversed) ----
__global__ void k_conv(const float* __restrict__ x, const float* __restrict__ w,
                       const float* __restrict__ cb) {
    size_t idx = (size_t)blockIdx.x * blockDim.x + threadIdx.x;
    if (idx >= (size_t)Bsz * Ln * DM) return;
    int d = (int)(idx & (DM - 1));
    size_t bl = idx >> 6;
    int l = (int)(bl % Ln);
    int b = (int)(bl / Ln);
    const float* xp = x + (size_t)b * Tn + 3 * (size_t)l;
    float v = cb[d] + xp[0] * w[d * 3 + 0] + xp[1] * w[d * 3 + 1] + xp[2] * w[d * 3 + 2];
    g_z[0][bl * DM + d] = v;
    g_z[1][((size_t)b * Ln + (Ln - 1 - l)) * DM + d] = v;
}

// ---------------- k3pre: A = -exp(Alog), fast flag per (c,d) --------------
__global__ void k3pre(int p, const float* __restrict__ f_alog, const float* __restrict__ b_alog) {
    int c = blockIdx.x;
    int d = threadIdx.x;
    const float* alog = (c ? b_alog : f_alog) + ((size_t)p * DI + d) * NSt;
    bool fast = true;
#pragma unroll
    for (int n = 0; n < NSt; n++) {
        float a = -__expf(alog[n]);
        g_A[c][d * NSt + n] = a;
        float tgt = (float)(n + 1);
        if (fabsf(a + tgt) > 1e-5f * tgt) fast = false;
    }
    g_fast[c][d] = fast ? 1 : 0;
}

// ---------------- k1: LN + in_proj (64->256) via f32x2 --------------------
// 256 thr = 8 warps x 8 rows = 64 rows/block. grid (B*L/64, 2)
__global__ void __launch_bounds__(256) k1_ln_inproj(int p,
        const float* __restrict__ f_lnw, const float* __restrict__ f_lnb,
        const float* __restrict__ f_inw,
        const float* __restrict__ b_lnw, const float* __restrict__ b_lnb,
        const float* __restrict__ b_inw) {
    extern __shared__ float sm1[];
    float* Ws = sm1;                 // [128 pairs][65 pitch] float2 (xi_q, zg_q)
    float* us = sm1 + 128 * 65 * 2;  // [64 rows][64 d] float2 dup (u,u)
    int c = blockIdx.y;
    const float* lnw = (c ? b_lnw : f_lnw) + p * DM;
    const float* lnb = (c ? b_lnb : f_lnb) + p * DM;
    const float* inw = (c ? b_inw : f_inw) + (size_t)p * 256 * DM;

    for (int s = threadIdx.x; s < 128 * 64; s += 256) {
        int q = s >> 6, d = s & 63;
        float lo = inw[q * 64 + d];
        float hi = inw[(q + 128) * 64 + d];
        *(float2*)&Ws[(q * 65 + d) * 2] = make_float2(lo, hi);
    }

    int warp = threadIdx.x >> 5, lane = threadIdx.x & 31;
    size_t row0 = (size_t)blockIdx.x * 64 + warp * 8;
    const float* zb = g_z[c];
    float lw0 = lnw[lane], lw1 = lnw[lane + 32];
    float lb0 = lnb[lane], lb1 = lnb[lane + 32];
    float* up = us + (size_t)warp * 8 * 64 * 2;

#pragma unroll
    for (int r = 0; r < 8; r++) {
        size_t row = row0 + r;
        float v0 = zb[row * DM + lane], v1 = zb[row * DM + lane + 32];
        float s = v0 + v1, ss = v0 * v0 + v1 * v1;
#pragma unroll
        for (int o = 16; o; o >>= 1) {
            s  += __shfl_xor_sync(0xffffffffu, s, o);
            ss += __shfl_xor_sync(0xffffffffu, ss, o);
        }
        float mean = s * (1.0f / 64.0f);
        float var  = ss * (1.0f / 64.0f) - mean * mean;
        float rstd = rsqrtf(var + 1e-5f);
        float u0 = (v0 - mean) * rstd * lw0 + lb0;
        float u1 = (v1 - mean) * rstd * lw1 + lb1;
        *(float2*)&up[(r * 64 + lane) * 2]      = make_float2(u0, u0);
        *(float2*)&up[(r * 64 + lane + 32) * 2] = make_float2(u1, u1);
    }
    __syncthreads();

    const ull* Wp = (const ull*)Ws;
    const ull* Up = (const ull*)us + (size_t)warp * 8 * 64;
    const ull* W0 = Wp + (size_t)lane * 65;
    const ull* W1 = Wp + (size_t)(32 + lane) * 65;
    const ull* W2 = Wp + (size_t)(64 + lane) * 65;
    const ull* W3 = Wp + (size_t)(96 + lane) * 65;

    ull acc[4][8];
#pragma unroll
    for (int j = 0; j < 4; j++)
#pragma unroll
        for (int r = 0; r < 8; r++) acc[j][r] = 0ull;

#pragma unroll 2
    for (int d = 0; d < 64; d++) {
        ull w0 = W0[d], w1 = W1[d], w2 = W2[d], w3 = W3[d];
#pragma unroll
        for (int r = 0; r < 8; r++) {
            ull u = Up[r * 64 + d];
            fma2(acc[0][r], w0, u);
            fma2(acc[1][r], w1, u);
            fma2(acc[2][r], w2, u);
            fma2(acc[3][r], w3, u);
        }
    }

    float* xiraw = g_xiraw[c];
    float* szg = g_szg[c];
#pragma unroll
    for (int j = 0; j < 4; j++) {
        int q = j * 32 + lane;
#pragma unroll
        for (int r = 0; r < 8; r++) {
            float2 v = up2(acc[j][r]);
            xiraw[(row0 + r) * DI + q] = v.x;
            szg[(row0 + r) * DI + q]   = silu_f(v.y);
        }
    }
}

// ---------------- k2: depthwise causal conv(4)+silu, xp proj(->20), dt ----
__global__ void k2_conv_xp_dt(int p,
                              const float* __restrict__ f_cvw, const float* __restrict__ f_cvb,
                              const float* __restrict__ f_xpw, const float* __restrict__ f_dtw,
                              const float* __restrict__ f_dtb,
                              const float* __restrict__ b_cvw, const float* __restrict__ b_cvb,
                              const float* __restrict__ b_xpw, const float* __restrict__ b_dtw,
                              const float* __restrict__ b_dtb) {
    extern __shared__ float sm2[];
    float* raw = sm2;                    // (TL+3)*128
    float* xis = raw + (TL + 3) * DI;    // TL*128
    float* bcr = xis + TL * DI;          // TL*20
    float* xw  = bcr + TL * 20;          // [128][20]
    float* dtw = xw + DI * 20;           // 128*4
    float* cvw = dtw + DI * 4;           // 128*4
    float* cvb = cvw + DI * 4;           // 128
    float* dtb = cvb + DI;               // 128

    int c = blockIdx.y;
    const float* cvwg = (c ? b_cvw : f_cvw) + (size_t)p * DI * 4;
    const float* cvbg = (c ? b_cvb : f_cvb) + p * DI;
    const float* xpwg = (c ? b_xpw : f_xpw) + (size_t)p * 20 * DI;
    const float* dtwg = (c ? b_dtw : f_dtw) + (size_t)p * DI * 4;
    const float* dtbg = (c ? b_dtb : f_dtb) + p * DI;

    for (int s = threadIdx.x; s < 20 * DI; s += blockDim.x) {
        int e = s >> 7, d = s & 127;
        xw[d * 20 + e] = xpwg[s];
    }
    for (int s = threadIdx.x; s < DI * 4; s += blockDim.x) { dtw[s] = dtwg[s]; cvw[s] = cvwg[s]; }
    for (int s = threadIdx.x; s < DI; s += blockDim.x) { cvb[s] = cvbg[s]; dtb[s] = dtbg[s]; }

    int chunk = blockIdx.x % (Ln / TL);
    int b = blockIdx.x / (Ln / TL);
    int l0 = chunk * TL;
    const float* xiraw = g_xiraw[c] + (size_t)b * Ln * DI;

    for (int s = threadIdx.x; s < (TL + 3) * DI; s += blockDim.x) {
        int r = s >> 7, d = s & 127;
        int l = l0 - 3 + r;
        raw[s] = (l >= 0) ? xiraw[(size_t)l * DI + d] : 0.0f;
    }
    __syncthreads();

    float* xig = g_xi[c] + (size_t)b * Ln * DI;
    for (int s = threadIdx.x; s < TL * DI; s += blockDim.x) {
        int r = s >> 7, d = s & 127;
        float a = cvb[d];
#pragma unroll
        for (int j = 0; j < 4; j++) a = fmaf(raw[(r + j) * DI + d], cvw[d * 4 + j], a);
        a = silu_f(a);
        xis[s] = a;
        xig[(size_t)(l0 + r) * DI + d] = a;
    }
    __syncthreads();

    int warp = threadIdx.x >> 5, lane = threadIdx.x & 31;
    float* bcg = g_bc[c] + (size_t)b * Ln * 16;
    for (int r = warp; r < TL; r += 8) {
        if (lane < 20) {
            float a = 0.0f;
            const float* xr = xis + r * DI;
#pragma unroll 8
            for (int d = 0; d < DI; d++) a = fmaf(xr[d], xw[d * 20 + lane], a);
            bcr[r * 20 + lane] = a;
            if (lane >= 4) bcg[(size_t)(l0 + r) * 16 + (lane - 4)] = a;
        }
    }
    __syncthreads();

    float* dtg = g_dt[c] + (size_t)b * Ln * DI;
    for (int s = threadIdx.x; s < TL * DI; s += blockDim.x) {
        int r = s >> 7, d = s & 127;
        const float* q = bcr + r * 20;
        float v = dtb[d];
#pragma unroll
        for (int j = 0; j < 4; j++) v = fmaf(q[j], dtw[d * 4 + j], v);
        v = fmaxf(v, 0.0f) + log1pf(__expf(-fabsf(v)));
        dtg[(size_t)(l0 + r) * DI + d] = v;
    }
}

// ---------------- k3a: chunked local scan (h0=0), writes y_partial, S, hf -
// grid (Bsz*NCH, 2), block 128
__global__ void k3a_scan(int p, const float* __restrict__ f_Dp, const float* __restrict__ b_Dp) {
    int c = blockIdx.y;
    int bm = blockIdx.x;
    int b = bm / NCH, m = bm % NCH;
    int d = threadIdx.x;
    float Dv = ((c ? b_Dp : f_Dp) + p * DI)[d];
    int fast = g_fast[c][d];
    float A[NSt];
#pragma unroll
    for (int n = 0; n < NSt; n++) A[n] = g_A[c][d * NSt + n];

    float h[NSt];
#pragma unroll
    for (int n = 0; n < NSt; n++) h[n] = 0.0f;
    float S = 0.0f;

    size_t base = ((size_t)b * Ln + (size_t)m * CHK) * DI + d;
    float* dtp = g_dt[c] + base;
    const float* xip = g_xi[c] + base;
    float* yp = g_xiraw[c] + base;
    const float4* bcp = (const float4*)(g_bc[c] + ((size_t)b * Ln + (size_t)m * CHK) * 16);

    if (fast) {
#pragma unroll 2
        for (int l = 0; l < CHK; l++) {
            float dtv = dtp[(size_t)l * DI];
            float xv  = xip[(size_t)l * DI];
            S += dtv;
            dtp[(size_t)l * DI] = S;
            float4 q0 = bcp[l * 4 + 0], q1 = bcp[l * 4 + 1];
            float4 q2 = bcp[l * 4 + 2], q3 = bcp[l * 4 + 3];
            float Bv[8] = {q0.x, q0.y, q0.z, q0.w, q1.x, q1.y, q1.z, q1.w};
            float Cv[8] = {q2.x, q2.y, q2.z, q2.w, q3.x, q3.y, q3.z, q3.w};
            float dx = dtv * xv;
            float y = xv * Dv;
            float w = __expf(-dtv);
            float e = w;
#pragma unroll
            for (int n = 0; n < NSt; n++) {
                h[n] = fmaf(h[n], e, dx * Bv[n]);
                y = fmaf(h[n], Cv[n], y);
                e *= w;
            }
            yp[(size_t)l * DI] = y;
        }
    } else {
        for (int l = 0; l < CHK; l++) {
            float dtv = dtp[(size_t)l * DI];
            float xv  = xip[(size_t)l * DI];
            S += dtv;
            dtp[(size_t)l * DI] = S;
            float4 q0 = bcp[l * 4 + 0], q1 = bcp[l * 4 + 1];
            float4 q2 = bcp[l * 4 + 2], q3 = bcp[l * 4 + 3];
            float Bv[8] = {q0.x, q0.y, q0.z, q0.w, q1.x, q1.y, q1.z, q1.w};
            float Cv[8] = {q2.x, q2.y, q2.z, q2.w, q3.x, q3.y, q3.z, q3.w};
            float dx = dtv * xv;
            float y = xv * Dv;
#pragma unroll
            for (int n = 0; n < NSt; n++) {
                float e = __expf(dtv * A[n]);
                h[n] = fmaf(h[n], e, dx * Bv[n]);
                y = fmaf(h[n], Cv[n], y);
            }
            yp[(size_t)l * DI] = y;
        }
    }

    float4* hfp = (float4*)(g_hf[c] + (((size_t)b * NCH + m) * DI + d) * NSt);
    hfp[0] = make_float4(h[0], h[1], h[2], h[3]);
    hfp[1] = make_float4(h[4], h[5], h[6], h[7]);
}

// ---------------- k3b: chain chunk states sequentially --------------------
// grid (Bsz, 2), block 128
__global__ void k3b_comb() {
    int c = blockIdx.y, b = blockIdx.x, d = threadIdx.x;
    float A[NSt];
#pragma unroll
    for (int n = 0; n < NSt; n++) A[n] = g_A[c][d * NSt + n];
    float hi[NSt];
#pragma unroll
    for (int n = 0; n < NSt; n++) hi[n] = 0.0f;

    for (int m = 0; m < NCH; m++) {
        size_t off = (((size_t)b * NCH + m) * DI + d) * NSt;
        float4* hip = (float4*)(g_hi[c] + off);
        hip[0] = make_float4(hi[0], hi[1], hi[2], hi[3]);
        hip[1] = make_float4(hi[4], hi[5], hi[6], hi[7]);
        float Send = g_dt[c][((size_t)b * Ln + (size_t)m * CHK + CHK - 1) * DI + d];
        const float4* hfp = (const float4*)(g_hf[c] + off);
        float4 f0 = hfp[0], f1 = hfp[1];
        float hf[8] = {f0.x, f0.y, f0.z, f0.w, f1.x, f1.y, f1.z, f1.w};
#pragma unroll
        for (int n = 0; n < NSt; n++) hi[n] = fmaf(__expf(A[n] * Send), hi[n], hf[n]);
    }
}

// ---------------- k4: correction + *silu(zg) + out proj (f32x2) + residual
// 256 thr = 8 warps x 8 rows = 64 rows/block. grid (B*L/64, 2)
__global__ void __launch_bounds__(256) k4_outproj(int p, const float* __restrict__ f_ow,
                                                  const float* __restrict__ b_ow) {
    extern __shared__ float sm4[];
    float* ws = sm4;                 // [128 d][66] float2 dup (w,w)
    float* us = sm4 + 128 * 66 * 2;  // [32 rowpairs][128 d] float2 (u_even,u_odd)
    int c = blockIdx.y;
    const float* ow = (c ? b_ow : f_ow) + (size_t)p * DM * DI;

    for (int s = threadIdx.x; s < DM * DI; s += 256) {
        int mm = s >> 7, d = s & 127;
        float v = ow[s];
        int j = mm >> 5, ln = mm & 31;
        *(float2*)&ws[(d * 66 + j * 33 + ln) * 2] = make_float2(v, v);
    }

    size_t row0 = (size_t)blockIdx.x * 64;
    const float* yb  = g_xiraw[c];
    const float* Sb  = g_dt[c];
    const float* sgb = g_szg[c];
    const float* bcb = g_bc[c];
    const float* hib = g_hi[c];

    for (int s = threadIdx.x; s < 64 * DI; s += 256) {
        int r = s >> 7, d = s & 127;
        unsigned int row = (unsigned int)(row0 + r);
        unsigned int b2 = row / Ln;
        unsigned int l  = row % Ln;
        unsigned int m  = l / CHK;
        float y  = yb[(size_t)row * DI + d];
        float S  = Sb[(size_t)row * DI + d];
        float sg = sgb[(size_t)row * DI + d];
        const float4* C4 = (const float4*)(bcb + (size_t)row * 16 + 8);
        float4 c0 = C4[0], c1 = C4[1];
        float Cv[8] = {c0.x, c0.y, c0.z, c0.w, c1.x, c1.y, c1.z, c1.w};
        const float4* H4 = (const float4*)(hib + (((size_t)b2 * NCH + m) * DI + d) * NSt);
        float4 h0 = H4[0], h1 = H4[1];
        float Hv[8] = {h0.x, h0.y, h0.z, h0.w, h1.x, h1.y, h1.z, h1.w};
        float corr = 0.0f;
        if (g_fast[c][d]) {
            float e = __expf(-S), ep = e;
#pragma unroll
            for (int n = 0; n < NSt; n++) { corr = fmaf(Cv[n] * Hv[n], ep, corr); ep *= e; }
        } else {
#pragma unroll
            for (int n = 0; n < NSt; n++)
                corr = fmaf(Cv[n] * Hv[n], __expf(g_A[c][d * NSt + n] * S), corr);
        }
        float u = (y + corr) * sg;
        us[(((r >> 1) * DI + d) * 2) + (r & 1)] = u;
    }
    __syncthreads();

    int warp = threadIdx.x >> 5, lane = threadIdx.x & 31;
    const ull* Wp = (const ull*)ws;
    const ull* Up = (const ull*)us + (size_t)warp * 4 * DI;
    float* zb = g_z[c];
    size_t rw0 = row0 + (size_t)warp * 8;

    ull acc[2][4];
#pragma unroll
    for (int j = 0; j < 2; j++) {
        int mm = j * 32 + lane;
#pragma unroll
        for (int rp = 0; rp < 4; rp++)
            acc[j][rp] = pk2(zb[(rw0 + 2 * rp) * DM + mm], zb[(rw0 + 2 * rp + 1) * DM + mm]);
    }

#pragma unroll 2
    for (int d = 0; d < DI; d++) {
        ull w0 = Wp[d * 66 + lane];
        ull w1 = Wp[d * 66 + 33 + lane];
#pragma unroll
        for (int rp = 0; rp < 4; rp++) {
            ull u = Up[rp * DI + d];
            fma2(acc[0][rp], w0, u);
            fma2(acc[1][rp], w1, u);
        }
    }

#pragma unroll
    for (int j = 0; j < 2; j++) {
        int mm = j * 32 + lane;
#pragma unroll
        for (int rp = 0; rp < 4; rp++) {
            float2 v = up2(acc[j][rp]);
            zb[(rw0 + 2 * rp) * DM + mm]     = v.x;
            zb[(rw0 + 2 * rp + 1) * DM + mm] = v.y;
        }
    }
}

// ---------------- k5: classifier ------------------------------------------
__global__ void k5_cls(const float* __restrict__ cw, const float* __restrict__ cb,
                       float* __restrict__ out) {
    __shared__ float hh[2 * DM];
    int b = blockIdx.x;
    int t = threadIdx.x;
    if (t < DM) hh[t] = g_z[0][((size_t)b * Ln + (Ln - 1)) * DM + t];
    else if (t < 2 * DM) hh[t] = g_z[1][((size_t)b * Ln + (Ln - 1)) * DM + (t - DM)];
    __syncthreads();
    float a = cb[t];
    const float* wr = cw + (size_t)t * 2 * DM;
#pragma unroll 8
    for (int j = 0; j < 2 * DM; j++) a = fmaf(hh[j], wr[j], a);
    out[(size_t)b * 256 + t] = a;
}

// ---------------- launch ---------------------------------------------------
extern "C" void kernel_launch(void* const* d_in, const int* in_sizes, int n_in,
                              void* d_out, int out_size) {
    const float* x      = (const float*)d_in[0];
    const float* conv_w = (const float*)d_in[1];
    const float* conv_b = (const float*)d_in[2];
    const float* F[11];
    const float* Bp[11];
    for (int i = 0; i < 11; i++) {
        F[i]  = (const float*)d_in[3 + i];
        Bp[i] = (const float*)d_in[14 + i];
    }
    const float* cls_w = (const float*)d_in[25];
    const float* cls_b = (const float*)d_in[26];
    float* out = (float*)d_out;

    const int smem1 = (128 * 65 * 2 + 64 * 64 * 2) * 4;
    const int smem2 = ((TL + 3) * DI + TL * DI + TL * 20 + DI * 20 + DI * 4 + DI * 4 + DI + DI) * 4;
    const int smem4 = (128 * 66 * 2 + 32 * 128 * 2) * 4;
    cudaFuncSetAttribute(k1_ln_inproj, cudaFuncAttributeMaxDynamicSharedMemorySize, smem1);
    cudaFuncSetAttribute(k2_conv_xp_dt, cudaFuncAttributeMaxDynamicSharedMemorySize, smem2);
    cudaFuncSetAttribute(k4_outproj, cudaFuncAttributeMaxDynamicSharedMemorySize, smem4);

    k_conv<<<(Bsz * Ln * DM + 255) / 256, 256>>>(x, conv_w, conv_b);

    for (int p = 0; p < NBk; p++) {
        k3pre<<<2, DI>>>(p, F[8], Bp[8]);
        k1_ln_inproj<<<dim3(Bsz * Ln / 64, 2), 256, smem1>>>(
            p, F[0], F[1], F[2], Bp[0], Bp[1], Bp[2]);
        k2_conv_xp_dt<<<dim3(Bsz * (Ln / TL), 2), 256, smem2>>>(
            p, F[3], F[4], F[5], F[6], F[7], Bp[3], Bp[4], Bp[5], Bp[6], Bp[7]);
        k3a_scan<<<dim3(Bsz * NCH, 2), DI>>>(p, F[9], Bp[9]);
        k3b_comb<<<dim3(Bsz, 2), DI>>>();
        k4_outproj<<<dim3(Bsz * Ln / 64, 2), 256, smem4>>>(p, F[10], Bp[10]);
    }

    k5_cls<<<Bsz, 256>>>(cls_w, cls_b, out);
}